// round 8
// baseline (speedup 1.0000x reference)
#include <cuda_runtime.h>
#include <math.h>

#define Wd 128
#define Hd 128
#define Fd 1000
#define NPIX (Wd*Hd)
#define NBLK 128           // 8 x 16 tiles of 16x8 pixels
#define EPSv 1e-10f
#define SIGMAv 1e-4f
#define BTH 0.055f         // cull threshold (>= sqrt(TCUT))
#define TCUT 3.0e-3f       // exp(-30): 1-p == 1.0f exactly in fp32 beyond this
#define PXS (2.0f / 127.0f)

// -------- persistent scratch (no allocations allowed) --------
__device__ float4 g_f1[Fd];        // A0, Bx0, By0, inv_area (A0=-1e30 sentinel if !ok)
__device__ float4 g_f2[Fd];        // A1, Bx1, By1, -
__device__ float4 g_f3[Fd];        // z0, z1, z2, -
__device__ float  g_fnrm[Fd * 3];
__device__ float  g_fuv[Fd * 6];

// -------- grid barrier (self-resetting each launch) --------
__device__ unsigned g_count = 0;
__device__ unsigned g_gen   = 0;

__device__ __forceinline__ void grid_barrier()
{
    __syncthreads();
    if (threadIdx.x == 0) {
        volatile unsigned* vgen = &g_gen;
        unsigned my = *vgen;
        __threadfence();
        unsigned arrived = atomicAdd(&g_count, 1);
        if (arrived == NBLK - 1) {
            g_count = 0;
            __threadfence();
            atomicAdd(&g_gen, 1);
        } else {
            while (*vgen == my) { }
            __threadfence();
        }
    }
    __syncthreads();
}

// ============================================================
// Single kernel, 128 blocks x 128 threads, 1 thread = 1 pixel.
//  Phase A: face setup once (8 faces/block, blocks 0..124)
//  barrier
//  Phase B: block culls ALL 1000 faces vs its 16x8 tile,
//           compacts survivors (face-ordered) into smem,
//           each thread loops survivors and shades inline.
// ============================================================
__global__ __launch_bounds__(128, 1)
void render_all(const float* __restrict__ pts,
                const int*   __restrict__ faces,
                const float* __restrict__ rot,
                const float* __restrict__ pos,
                const float* __restrict__ proj,
                const float* __restrict__ uv,
                const int*   __restrict__ ft,
                const float* __restrict__ tex,
                const float* __restrict__ light,
                float* __restrict__ out)
{
    const int tid = threadIdx.x;
    const int bid = blockIdx.x;
    const int lane = tid & 31;
    const int wrp  = tid >> 5;

    __shared__ float4 c1[Fd], c2[Fd], c3[Fd];   // survivors (47 KB)
    __shared__ unsigned s_masks[4][8];
    __shared__ int s_wcnt[4];

    // ---------------- Phase A: face setup (once across grid) -------------
    if (bid < 125 && tid < 8) {
        int f = bid * 8 + tid;

        float R0 = rot[0], R1 = rot[1], R2 = rot[2];
        float R3 = rot[3], R4 = rot[4], R5 = rot[5];
        float R6 = rot[6], R7 = rot[7], R8 = rot[8];
        float cc0 = pos[0], cc1 = pos[1], cc2 = pos[2];
        float pj0 = proj[0], pj1 = proj[1], pj2 = proj[2];

        float pcx[3], pcy[3], pcz[3], sx[3], sy[3];
        #pragma unroll
        for (int k = 0; k < 3; k++) {
            int vi = faces[f * 3 + k];
            const float* p = pts + vi * 3;
            float d0 = p[0] - cc0, d1 = p[1] - cc1, d2 = p[2] - cc2;
            float x = R0 * d0 + R1 * d1 + R2 * d2;
            float y = R3 * d0 + R4 * d1 + R5 * d2;
            float z = R6 * d0 + R7 * d1 + R8 * d2;
            pcx[k] = x; pcy[k] = y; pcz[k] = z;
            float Z = z * pj2;
            sx[k] = (x * pj0) / Z;
            sy[k] = (y * pj1) / Z;
        }

        float ax = pcx[1] - pcx[0], ay = pcy[1] - pcy[0], az = pcz[1] - pcz[0];
        float bx = pcx[2] - pcx[0], by = pcy[2] - pcy[0], bz = pcz[2] - pcz[0];
        float nx = ay * bz - az * by;
        float ny = az * bx - ax * bz;
        float nz = ax * by - ay * bx;

        float nn = sqrtf(nx * nx + ny * ny + nz * nz);
        float inv = 1.0f / fmaxf(nn, EPSv);
        float* onrm = out + NPIX * 3 + NPIX;
        onrm[f * 3 + 0] = nx * inv;
        onrm[f * 3 + 1] = ny * inv;
        onrm[f * 3 + 2] = nz * inv;
        g_fnrm[f * 3 + 0] = nx;
        g_fnrm[f * 3 + 1] = ny;
        g_fnrm[f * 3 + 2] = nz;
        #pragma unroll
        for (int k = 0; k < 3; k++) {
            int ti = ft[f * 3 + k];
            g_fuv[f * 6 + 2 * k + 0] = uv[ti * 2 + 0];
            g_fuv[f * 6 + 2 * k + 1] = uv[ti * 2 + 1];
        }

        bool valid = nz > 0.0f;

        float A0  = sx[1] * sy[2] - sx[2] * sy[1];
        float Bx0 = sy[1] - sy[2];
        float By0 = sx[2] - sx[1];
        float A1  = sx[2] * sy[0] - sx[0] * sy[2];
        float Bx1 = sy[2] - sy[0];
        float By1 = sx[0] - sx[2];
        float A2  = sx[0] * sy[1] - sx[1] * sy[0];
        float area = A0 + A1 + A2;
        bool areaok = fabsf(area) > EPSv;
        float ia = areaok ? (1.0f / area) : 0.0f;
        bool ok = valid && areaok;

        g_f1[f] = ok ? make_float4(A0, Bx0, By0, ia)
                     : make_float4(-1e30f, 0.0f, 0.0f, 1.0f);
        g_f2[f] = make_float4(A1, Bx1, By1, 0.0f);
        g_f3[f] = make_float4(pcz[0], pcz[1], pcz[2], 0.0f);
    }

    grid_barrier();

    // ---------------- Phase B: tile cull over ALL faces -------------------
    // tile: 16 px wide x 8 px tall
    const int tx = bid & 7;        // 0..7  -> x0 = tx*16
    const int ty = bid >> 3;       // 0..15 -> h0 = ty*8
    const int x0 = tx * 16, h0 = ty * 8;

    float pxA = -1.0f + (float)(x0)      * PXS;
    float pxB = -1.0f + (float)(x0 + 15) * PXS;
    float pyA =  1.0f - (float)(h0)      * PXS;
    float pyB =  1.0f - (float)(h0 + 7)  * PXS;

    // pass 1: flags (warp w owns faces [w*250, w*250+250), ascending order)
    const int fbase = wrp * 250;
    int cnt = 0;
    #pragma unroll
    for (int r = 0; r < 8; r++) {
        int off = r * 32 + lane;
        bool aliveflag = false;
        if (off < 250) {
            int f = fbase + off;
            float4 v1 = g_f1[f];
            float4 v2 = g_f2[f];
            float b0c0 = (v1.x + pxA * v1.y + pyA * v1.z) * v1.w;
            float b0c1 = (v1.x + pxB * v1.y + pyA * v1.z) * v1.w;
            float b0c2 = (v1.x + pxA * v1.y + pyB * v1.z) * v1.w;
            float b0c3 = (v1.x + pxB * v1.y + pyB * v1.z) * v1.w;
            float b1c0 = (v2.x + pxA * v2.y + pyA * v2.z) * v1.w;
            float b1c1 = (v2.x + pxB * v2.y + pyA * v2.z) * v1.w;
            float b1c2 = (v2.x + pxA * v2.y + pyB * v2.z) * v1.w;
            float b1c3 = (v2.x + pxB * v2.y + pyB * v2.z) * v1.w;
            float m0 = fmaxf(fmaxf(b0c0, b0c1), fmaxf(b0c2, b0c3));
            float m1 = fmaxf(fmaxf(b1c0, b1c1), fmaxf(b1c2, b1c3));
            float smin = fminf(fminf(b0c0 + b1c0, b0c1 + b1c1),
                               fminf(b0c2 + b1c2, b0c3 + b1c3));
            float m2 = 1.0f - smin;
            aliveflag = (m0 >= -BTH) && (m1 >= -BTH) && (m2 >= -BTH);
        }
        unsigned m = __ballot_sync(0xffffffffu, aliveflag);
        if (lane == 0) s_masks[wrp][r] = m;
        cnt += __popc(m);
    }
    if (lane == 0) s_wcnt[wrp] = cnt;
    __syncthreads();

    int wb0 = s_wcnt[0];
    int wb1 = wb0 + s_wcnt[1];
    int wb2 = wb1 + s_wcnt[2];
    const int ns = wb2 + s_wcnt[3];
    int wbase = (wrp == 0) ? 0 : (wrp == 1) ? wb0 : (wrp == 2) ? wb1 : wb2;

    // pass 2: write survivor payloads at ordered offsets
    {
        int pre = 0;
        #pragma unroll
        for (int r = 0; r < 8; r++) {
            unsigned m = s_masks[wrp][r];
            if (m) {
                int off = r * 32 + lane;
                if ((m >> lane) & 1u) {
                    int f = fbase + off;
                    int o = wbase + pre + __popc(m & ((1u << lane) - 1u));
                    float4 v1 = g_f1[f];
                    float4 v2 = g_f2[f];
                    float4 v3 = g_f3[f];
                    v2.w = __int_as_float(f);     // stash global face id
                    c1[o] = v1;
                    c2[o] = v2;
                    c3[o] = v3;
                }
                pre += __popc(m);
            }
        }
    }
    __syncthreads();

    // ---------------- raster loop + inline shade (1 thread = 1 pixel) -----
    const int lx = tid & 15, ly = tid >> 4;
    const int w = x0 + lx;
    const int h = h0 + ly;
    const float pxv = -1.0f + (float)w * PXS;
    const float pyv =  1.0f - (float)h * PXS;

    float best = -1000000000.0f;
    int   idx  = 0;
    float bw0 = 0.0f, bw1 = 0.0f;
    float prod = 1.0f;

    for (int i = 0; i < ns; i++) {
        float4 a = c1[i];
        float4 b = c2[i];
        float b0 = (a.x + pxv * a.y + pyv * a.z) * a.w;
        float b1 = (b.x + pxv * b.y + pyv * b.z) * a.w;
        float b2 = 1.0f - b0 - b1;
        float bmin = fminf(b0, fminf(b1, b2));

        float d = fmaxf(-bmin, 0.0f);
        float t = d * d;
        float fac = (t < TCUT) ? (1.0f - __expf(t * (-1.0f / SIGMAv))) : 1.0f;
        prod *= fac;

        if (bmin >= 0.0f) {
            float4 z = c3[i];
            float zp = b0 * z.x + b1 * z.y + b2 * z.z;
            if (zp > best) {           // ascending face order; strict > = argmax-first
                best = zp; idx = __float_as_int(b.w); bw0 = b0; bw1 = b1;
            }
        }
    }

    // shade
    {
        float vis = (best > -5.0e8f) ? 1.0f : 0.0f;
        float w2 = 1.0f - bw0 - bw1;
        float sumw = bw0 + bw1 + w2;

        float nx = g_fnrm[idx * 3 + 0];
        float ny = g_fnrm[idx * 3 + 1];
        float nz = g_fnrm[idx * 3 + 2];
        float fnx = nx * sumw * vis;
        float fny = ny * sumw * vis;
        float fnz = nz * sumw * vis;

        const float* uvp = g_fuv + idx * 6;
        float u = (bw0 * uvp[0] + bw1 * uvp[2] + w2 * uvp[4]) * vis;
        float v = (bw0 * uvp[1] + bw1 * uvp[3] + w2 * uvp[5]) * vis;
        float hard = sumw * vis;

        float nn = sqrtf(fnx * fnx + fny * fny + fnz * fnz);
        float inv = 1.0f / fmaxf(nn, EPSv);
        float X = fnx * inv, Y = fny * inv, Z = fnz * inv;

        float shading =
            0.2820948f                    * __ldg(light + 0) +
            (0.4886025f * Y)              * __ldg(light + 1) +
            (0.4886025f * Z)              * __ldg(light + 2) +
            (0.4886025f * X)              * __ldg(light + 3) +
            (1.092548f * X * Y)           * __ldg(light + 4) +
            (1.092548f * Y * Z)           * __ldg(light + 5) +
            (0.3153916f * (3.0f * Z * Z - 1.0f)) * __ldg(light + 6) +
            (1.092548f * X * Z)           * __ldg(light + 7) +
            (0.5462742f * (X * X - Y * Y))* __ldg(light + 8);

        float uu = fminf(fmaxf(u, 0.0f), 1.0f) * 255.0f;
        float vv = fminf(fmaxf(v, 0.0f), 1.0f) * 255.0f;
        float x0f = floorf(uu), y0f = floorf(vv);
        int xi0 = (int)x0f, yi0 = (int)y0f;
        int xi1 = min(xi0 + 1, 255), yi1 = min(yi0 + 1, 255);
        float fx = uu - x0f, fy = vv - y0f;
        float omfx = 1.0f - fx, omfy = 1.0f - fy;

        int pix = h * Wd + w;
        #pragma unroll
        for (int c = 0; c < 3; c++) {
            const float* tc = tex + c * 65536;
            float c00 = __ldg(tc + yi0 * 256 + xi0);
            float c01 = __ldg(tc + yi0 * 256 + xi1);
            float c10 = __ldg(tc + yi1 * 256 + xi0);
            float c11 = __ldg(tc + yi1 * 256 + xi1);
            float col = (c00 * omfx + c01 * fx) * omfy + (c10 * omfx + c11 * fx) * fy;
            float r = col * shading * hard;
            out[pix * 3 + c] = fminf(fmaxf(r, 0.0f), 1.0f);
        }
        out[NPIX * 3 + pix] = 1.0f - prod;    // improb
    }
}

// ============================================================
// launch
// ============================================================
extern "C" void kernel_launch(void* const* d_in, const int* in_sizes, int n_in,
                              void* d_out, int out_size)
{
    const float* pts   = (const float*)d_in[0];   // (1,602,3)
    const int*   faces = (const int*)  d_in[1];   // (1000,3)
    const float* rot   = (const float*)d_in[2];   // (1,3,3)
    const float* pos   = (const float*)d_in[3];   // (1,3)
    const float* proj  = (const float*)d_in[4];   // (3,1)
    const float* uv    = (const float*)d_in[5];   // (1,602,2)
    const int*   ft    = (const int*)  d_in[6];   // (1000,3)
    const float* tex   = (const float*)d_in[7];   // (1,3,256,256)
    const float* light = (const float*)d_in[8];   // (1,9)

    float* out = (float*)d_out;
    // layout: imrender [0,49152) | improb [49152,65536) | normal1 [65536,68536)

    render_all<<<NBLK, 128>>>(pts, faces, rot, pos, proj, uv, ft,
                              tex, light, out);
}

// round 9
// speedup vs baseline: 2.1579x; 2.1579x over previous
#include <cuda_runtime.h>
#include <math.h>

#define Wd 128
#define Hd 128
#define Fd 1000
#define NCHUNK 8
#define FPC 125            // faces per chunk (8*125 = 1000, exact)
#define NPIX (Wd*Hd)
#define NBLK 512           // 64 tiles x 8 chunks
#define EPSv 1e-10f
#define SIGMAv 1e-4f
#define BTH 0.055f         // cull threshold (>= sqrt(TCUT))
#define TCUT 3.0e-3f       // exp(-30): 1-p == 1.0f exactly in fp32 beyond this
#define PXS (2.0f / 127.0f)

// -------- persistent scratch (no allocations allowed) --------
__device__ float  g_fnrm[Fd * 3];
__device__ float  g_fuv[Fd * 6];
__device__ float4 g_part[NCHUNK * NPIX];   // best_score, w0, w1, prod
__device__ int    g_pidx[NCHUNK * NPIX];

// -------- grid barrier (self-resetting each launch) --------
__device__ unsigned g_count = 0;
__device__ unsigned g_gen   = 0;

__device__ __forceinline__ void grid_barrier()
{
    __syncthreads();
    if (threadIdx.x == 0) {
        volatile unsigned* vgen = &g_gen;
        unsigned my = *vgen;
        __threadfence();
        unsigned arrived = atomicAdd(&g_count, 1);
        if (arrived == NBLK - 1) {
            g_count = 0;
            __threadfence();
            atomicAdd(&g_gen, 1);
        } else {
            while (*vgen == my) { }
            __threadfence();
        }
    }
    __syncthreads();
}

// ============================================================
// Single fused kernel (R6 structure, stall-optimized):
//  Phase A: per-block face setup of its 125-face chunk
//  Phase B: tile cull + in-order compaction + unrolled raster
//  barrier
//  Phase C: shade 32 px/block with batched reduction loads
// ============================================================
__global__ __launch_bounds__(256, 5)
void render_fused(const float* __restrict__ pts,
                  const int*   __restrict__ faces,
                  const float* __restrict__ rot,
                  const float* __restrict__ pos,
                  const float* __restrict__ proj,
                  const float* __restrict__ uv,
                  const int*   __restrict__ ft,
                  const float* __restrict__ tex,
                  const float* __restrict__ light,
                  float* __restrict__ out)
{
    const int tid   = threadIdx.x;
    const int bid   = blockIdx.x;
    const int tile  = bid & 63;
    const int chunk = bid >> 6;
    const int f0 = chunk * FPC;
    const int tx = tile & 7, ty = tile >> 3;

    __shared__ float4 s1[FPC], s2[FPC], s3[FPC];
    __shared__ float4 c1[FPC], c2[FPC], c3[FPC];
    __shared__ int    sflag[FPC];
    __shared__ int    s_n;

    // ---------------- Phase A: face setup + tile cull --------------------
    if (tid < FPC) {
        int f = f0 + tid;

        float R0 = rot[0], R1 = rot[1], R2 = rot[2];
        float R3 = rot[3], R4 = rot[4], R5 = rot[5];
        float R6 = rot[6], R7 = rot[7], R8 = rot[8];
        float cc0 = pos[0], cc1 = pos[1], cc2 = pos[2];
        float pj0 = proj[0], pj1 = proj[1], pj2 = proj[2];

        float pcx[3], pcy[3], pcz[3], sx[3], sy[3];
        #pragma unroll
        for (int k = 0; k < 3; k++) {
            int vi = faces[f * 3 + k];
            const float* p = pts + vi * 3;
            float d0 = p[0] - cc0, d1 = p[1] - cc1, d2 = p[2] - cc2;
            float x = R0 * d0 + R1 * d1 + R2 * d2;
            float y = R3 * d0 + R4 * d1 + R5 * d2;
            float z = R6 * d0 + R7 * d1 + R8 * d2;
            pcx[k] = x; pcy[k] = y; pcz[k] = z;
            float Z = z * pj2;
            sx[k] = (x * pj0) / Z;
            sy[k] = (y * pj1) / Z;
        }

        float ax = pcx[1] - pcx[0], ay = pcy[1] - pcy[0], az = pcz[1] - pcz[0];
        float bx = pcx[2] - pcx[0], by = pcy[2] - pcy[0], bz = pcz[2] - pcz[0];
        float nx = ay * bz - az * by;
        float ny = az * bx - ax * bz;
        float nz = ax * by - ay * bx;

        bool valid = nz > 0.0f;

        float A0  = sx[1] * sy[2] - sx[2] * sy[1];
        float Bx0 = sy[1] - sy[2];
        float By0 = sx[2] - sx[1];
        float A1  = sx[2] * sy[0] - sx[0] * sy[2];
        float Bx1 = sy[2] - sy[0];
        float By1 = sx[0] - sx[2];
        float A2  = sx[0] * sy[1] - sx[1] * sy[0];
        float area = A0 + A1 + A2;
        bool areaok = fabsf(area) > EPSv;
        float ia = areaok ? (1.0f / area) : 0.0f;
        bool ok = valid && areaok;

        float4 v1 = ok ? make_float4(A0, Bx0, By0, ia)
                       : make_float4(-1e30f, 0.0f, 0.0f, 1.0f);
        float4 v2 = make_float4(A1, Bx1, By1, __int_as_float(f));
        s1[tid] = v1;
        s2[tid] = v2;
        s3[tid] = make_float4(pcz[0], pcz[1], pcz[2], 0.0f);

        if (tile == 0) {
            float nn = sqrtf(nx * nx + ny * ny + nz * nz);
            float inv = 1.0f / fmaxf(nn, EPSv);
            float* onrm = out + NPIX * 3 + NPIX;
            onrm[f * 3 + 0] = nx * inv;
            onrm[f * 3 + 1] = ny * inv;
            onrm[f * 3 + 2] = nz * inv;
            g_fnrm[f * 3 + 0] = nx;
            g_fnrm[f * 3 + 1] = ny;
            g_fnrm[f * 3 + 2] = nz;
            #pragma unroll
            for (int k = 0; k < 3; k++) {
                int ti = ft[f * 3 + k];
                g_fuv[f * 6 + 2 * k + 0] = uv[ti * 2 + 0];
                g_fuv[f * 6 + 2 * k + 1] = uv[ti * 2 + 1];
            }
        }

        // tile cull via corner evaluation (b affine in px,py)
        float pxA = -1.0f + (float)(tx * 16)      * PXS;
        float pxB = -1.0f + (float)(tx * 16 + 15) * PXS;
        float pyA =  1.0f - (float)(ty * 16)      * PXS;
        float pyB =  1.0f - (float)(ty * 16 + 15) * PXS;

        float b0c[4], b1c[4];
        b0c[0] = (v1.x + pxA * v1.y + pyA * v1.z) * v1.w;
        b0c[1] = (v1.x + pxB * v1.y + pyA * v1.z) * v1.w;
        b0c[2] = (v1.x + pxA * v1.y + pyB * v1.z) * v1.w;
        b0c[3] = (v1.x + pxB * v1.y + pyB * v1.z) * v1.w;
        b1c[0] = (v2.x + pxA * v2.y + pyA * v2.z) * v1.w;
        b1c[1] = (v2.x + pxB * v2.y + pyA * v2.z) * v1.w;
        b1c[2] = (v2.x + pxA * v2.y + pyB * v2.z) * v1.w;
        b1c[3] = (v2.x + pxB * v2.y + pyB * v2.z) * v1.w;

        float m0 = fmaxf(fmaxf(b0c[0], b0c[1]), fmaxf(b0c[2], b0c[3]));
        float m1 = fmaxf(fmaxf(b1c[0], b1c[1]), fmaxf(b1c[2], b1c[3]));
        float s01min = fminf(fminf(b0c[0] + b1c[0], b0c[1] + b1c[1]),
                             fminf(b0c[2] + b1c[2], b0c[3] + b1c[3]));
        float m2 = 1.0f - s01min;
        sflag[tid] = (m0 >= -BTH) && (m1 >= -BTH) && (m2 >= -BTH);
    }
    __syncthreads();

    // ---------------- order-preserving compaction (warp 0) ---------------
    if (tid < 32) {
        int cnt = 0;
        #pragma unroll
        for (int r = 0; r < 4; r++) {
            int i = r * 32 + tid;
            bool p = (i < FPC) && (sflag[i] != 0);
            unsigned m = __ballot_sync(0xffffffffu, p);
            int ofs = cnt + __popc(m & ((1u << tid) - 1u));
            if (p) {
                c1[ofs] = s1[i];
                c2[ofs] = s2[i];   // .w carries global face id
                c3[ofs] = s3[i];
            }
            cnt += __popc(m);
        }
        if (tid == 0) s_n = cnt;
    }
    __syncthreads();

    // ---------------- Phase B: unrolled raster loop -----------------------
    {
        const int ns = s_n;
        int lx = tid & 15, ly = tid >> 4;
        int w = tx * 16 + lx;
        int h = ty * 16 + ly;
        float pxv = -1.0f + (float)w * PXS;
        float pyv =  1.0f - (float)h * PXS;

        float best = -1000000000.0f;
        int   bidx = f0;
        float bw0 = 0.0f, bw1 = 0.0f;
        float prod = 1.0f;

        #pragma unroll 4
        for (int i = 0; i < ns; i++) {
            float4 a = c1[i];
            float4 b = c2[i];
            float b0 = (a.x + pxv * a.y + pyv * a.z) * a.w;
            float b1 = (b.x + pxv * b.y + pyv * b.z) * a.w;
            float b2 = 1.0f - b0 - b1;
            float bmin = fminf(b0, fminf(b1, b2));

            float d = fmaxf(-bmin, 0.0f);
            float t = d * d;
            float fac = (t < TCUT) ? (1.0f - __expf(t * (-1.0f / SIGMAv))) : 1.0f;
            prod *= fac;

            if (bmin >= 0.0f) {
                float4 z = c3[i];
                float zp = b0 * z.x + b1 * z.y + b2 * z.z;
                if (zp > best) {       // ascending face order; strict > = argmax-first
                    best = zp; bidx = __float_as_int(b.w); bw0 = b0; bw1 = b1;
                }
            }
        }

        int pix = h * Wd + w;
        g_part[chunk * NPIX + pix] = make_float4(best, bw0, bw1, prod);
        g_pidx[chunk * NPIX + pix] = bidx;
    }

    grid_barrier();

    // ---------------- Phase C: shade (warp 0, 32 pixels per block) --------
    if (tid < 32) {
        int pix = bid * 32 + tid;

        // batched independent loads: one L2 round trip instead of 8 serial
        float4 pc[NCHUNK];
        int    pi[NCHUNK];
        #pragma unroll
        for (int c = 0; c < NCHUNK; c++) {
            pc[c] = g_part[c * NPIX + pix];
            pi[c] = g_pidx[c * NPIX + pix];
        }

        float best = pc[0].x, w0 = pc[0].y, w1 = pc[0].z, prod = pc[0].w;
        int idx = pi[0];
        #pragma unroll
        for (int c = 1; c < NCHUNK; c++) {
            prod *= pc[c].w;
            if (pc[c].x > best) {      // strict > keeps earliest chunk on ties
                best = pc[c].x; w0 = pc[c].y; w1 = pc[c].z; idx = pi[c];
            }
        }
        float vis = (best > -5.0e8f) ? 1.0f : 0.0f;
        float w2 = 1.0f - w0 - w1;
        float sumw = w0 + w1 + w2;

        float nx = g_fnrm[idx * 3 + 0];
        float ny = g_fnrm[idx * 3 + 1];
        float nz = g_fnrm[idx * 3 + 2];
        float fnx = nx * sumw * vis;
        float fny = ny * sumw * vis;
        float fnz = nz * sumw * vis;

        const float* uvp = g_fuv + idx * 6;
        float u = (w0 * uvp[0] + w1 * uvp[2] + w2 * uvp[4]) * vis;
        float v = (w0 * uvp[1] + w1 * uvp[3] + w2 * uvp[5]) * vis;
        float hard = sumw * vis;

        float nn = sqrtf(fnx * fnx + fny * fny + fnz * fnz);
        float inv = 1.0f / fmaxf(nn, EPSv);
        float X = fnx * inv, Y = fny * inv, Z = fnz * inv;

        float shading =
            0.2820948f                    * __ldg(light + 0) +
            (0.4886025f * Y)              * __ldg(light + 1) +
            (0.4886025f * Z)              * __ldg(light + 2) +
            (0.4886025f * X)              * __ldg(light + 3) +
            (1.092548f * X * Y)           * __ldg(light + 4) +
            (1.092548f * Y * Z)           * __ldg(light + 5) +
            (0.3153916f * (3.0f * Z * Z - 1.0f)) * __ldg(light + 6) +
            (1.092548f * X * Z)           * __ldg(light + 7) +
            (0.5462742f * (X * X - Y * Y))* __ldg(light + 8);

        float uu = fminf(fmaxf(u, 0.0f), 1.0f) * 255.0f;
        float vv = fminf(fmaxf(v, 0.0f), 1.0f) * 255.0f;
        float x0f = floorf(uu), y0f = floorf(vv);
        int x0 = (int)x0f, y0 = (int)y0f;
        int x1 = min(x0 + 1, 255), y1 = min(y0 + 1, 255);
        float fx = uu - x0f, fy = vv - y0f;
        float omfx = 1.0f - fx, omfy = 1.0f - fy;

        #pragma unroll
        for (int c = 0; c < 3; c++) {
            const float* tc = tex + c * 65536;
            float c00 = __ldg(tc + y0 * 256 + x0);
            float c01 = __ldg(tc + y0 * 256 + x1);
            float c10 = __ldg(tc + y1 * 256 + x0);
            float c11 = __ldg(tc + y1 * 256 + x1);
            float col = (c00 * omfx + c01 * fx) * omfy + (c10 * omfx + c11 * fx) * fy;
            float r = col * shading * hard;
            out[pix * 3 + c] = fminf(fmaxf(r, 0.0f), 1.0f);
        }
        out[NPIX * 3 + pix] = 1.0f - prod;    // improb
    }
}

// ============================================================
// launch
// ============================================================
extern "C" void kernel_launch(void* const* d_in, const int* in_sizes, int n_in,
                              void* d_out, int out_size)
{
    const float* pts   = (const float*)d_in[0];   // (1,602,3)
    const int*   faces = (const int*)  d_in[1];   // (1000,3)
    const float* rot   = (const float*)d_in[2];   // (1,3,3)
    const float* pos   = (const float*)d_in[3];   // (1,3)
    const float* proj  = (const float*)d_in[4];   // (3,1)
    const float* uv    = (const float*)d_in[5];   // (1,602,2)
    const int*   ft    = (const int*)  d_in[6];   // (1000,3)
    const float* tex   = (const float*)d_in[7];   // (1,3,256,256)
    const float* light = (const float*)d_in[8];   // (1,9)

    float* out = (float*)d_out;
    // layout: imrender [0,49152) | improb [49152,65536) | normal1 [65536,68536)

    render_fused<<<NBLK, 256>>>(pts, faces, rot, pos, proj, uv, ft,
                                tex, light, out);
}